// round 13
// baseline (speedup 1.0000x reference)
#include <cuda_runtime.h>
#include <cstdint>

// ---- problem constants ----
#define T_DIM   128
#define C_DIM   64
#define F_DIM   64
#define K_DIM   128          // filters = GEMM M
#define CP      62
#define N_TOTAL 4096
#define BN_EPS  1e-3f

#define NROWS   4            // fused rows per CTA -> GEMM N = 256
#define THREADS 512
#define NKC     24           // K chunks of 8 (K = 192)
#define NSTG    6            // stages of 4 kc
#define RING    3
#define LOOKA   2

// smem: Afrag[24][8 mtile][32 lane][4] floats, then Bs[3][4][256][8] floats
#define A_FLOATS 24576
#define STG_FLOATS 8192                  // 4 kc * 256 n * 8 k
#define B_FLOATS (RING * STG_FLOATS)     // 24576
#define SMEM_BYTES  ((A_FLOATS + B_FLOATS) * 4)   // 196608
#define STG_BYTES   (STG_FLOATS * 4)     // 32768

// epilogue smem reuse: per-warp [32 cp][pitch 68]
#define EPI_PITCH 68
#define EPI_WARP  (32 * EPI_PITCH)

__device__ __forceinline__ uint32_t smem_u32(const void* p) {
    uint32_t a;
    asm("{ .reg .u64 t; cvta.to.shared.u64 t, %1; cvt.u32.u64 %0, t; }" : "=r"(a) : "l"(p));
    return a;
}
__device__ __forceinline__ float tf32r(float v) {
    uint32_t u;
    asm("cvt.rna.tf32.f32 %0, %1;" : "=r"(u) : "f"(v));
    return __uint_as_float(u);
}
__device__ __forceinline__ void cp_async16(uint32_t dst, const void* src, int sz) {
    asm volatile("cp.async.ca.shared.global [%0], [%1], 16, %2;"
                 :: "r"(dst), "l"(src), "r"(sz) : "memory");
}
#define CP_COMMIT() asm volatile("cp.async.commit_group;" ::: "memory")
#define CP_WAIT1()  asm volatile("cp.async.wait_group 1;" ::: "memory")

__device__ __forceinline__ void lds128(uint32_t a, uint32_t* v) {
    asm volatile("ld.shared.v4.b32 {%0,%1,%2,%3}, [%4];"
                 : "=r"(v[0]), "=r"(v[1]), "=r"(v[2]), "=r"(v[3]) : "r"(a));
}
__device__ __forceinline__ uint32_t lds32(uint32_t a) {
    uint32_t v;
    asm volatile("ld.shared.b32 %0, [%1];" : "=r"(v) : "r"(a));
    return v;
}

__global__ __launch_bounds__(THREADS, 1)
void tccnn_mma5_kernel(const float* __restrict__ x,
                       const float* __restrict__ conv_w,
                       const float* __restrict__ conv_b,
                       const float* __restrict__ bn_gamma,
                       const float* __restrict__ bn_beta,
                       const float* __restrict__ bn_mean,
                       const float* __restrict__ bn_var,
                       float* __restrict__ out)
{
    extern __shared__ float smem[];
    float* As = smem;
    const uint32_t as_addr = smem_u32(smem);
    const uint32_t bs_addr = as_addr + A_FLOATS * 4;

    const int tid  = threadIdx.x;
    const int lane = tid & 31;
    const int wid  = tid >> 5;           // 0..15
    const int r    = lane >> 2;          // 0..7
    const int cql  = lane & 3;           // 0..3
    const int m0w  = (wid & 1) * 64;     // M origin: 2 m-warps
    const int nw   = wid >> 1;           // 0..7 n-slice
    const int row  = nw >> 1;            // fused row 0..3
    const int nhalf= (nw & 1) * 32;      // cp origin within row
    const int n0c  = blockIdx.x * NROWS;

    // ---- stage A as ready fragments:
    // frag f = kc*256 + mt8*32 + lane; [f] = {w[kl][ml], w[kl][ml+8], w[kh][ml], w[kh][ml+8]}
    // kl = 8*kc + (lane&3), kh = kl+4, ml = 16*mt8 + (lane>>2)
    #pragma unroll
    for (int i = 0; i < 12; ++i) {
        const int f   = tid + 512 * i;
        const int kc  = f >> 8;
        const int mt8 = (f >> 5) & 7;
        const int ln  = f & 31;
        const int kl  = 8 * kc + (ln & 3);
        const int kh2 = kl + 4;
        const int ml  = 16 * mt8 + (ln >> 2);
        float4 v;
        v.x = tf32r(conv_w[kl  * K_DIM + ml]);
        v.y = tf32r(conv_w[kl  * K_DIM + ml + 8]);
        v.z = tf32r(conv_w[kh2 * K_DIM + ml]);
        v.w = tf32r(conv_w[kh2 * K_DIM + ml + 8]);
        ((float4*)As)[f] = v;
    }

    // ---- cp.async source/dst bases (per thread) ----
    const int nb   = tid >> 1;           // 0..255 = rowt*64 + cpt
    const int half = tid & 1;
    const int cpt  = nb & 63;
    const float* xrow = x + (size_t)(n0c + (nb >> 6)) * (C_DIM * F_DIM);
    const float* psrc[3];
    int szs[3];
    #pragma unroll
    for (int kh = 0; kh < 3; ++kh) {
        const int c  = cpt + kh;
        psrc[kh] = xrow + ((c < C_DIM) ? c : 0) * F_DIM + 4 * half;
        szs[kh]  = (c < C_DIM) ? 16 : 0;
    }
    const uint32_t dstb = bs_addr + (uint32_t)((nb * 8 + 4 * half) * 4);

    // fill stage fsi into slot: sk = 4*fsi+j, kh = sk>>3, kw8 = sk&7
#define FILL_STAGE(FSI, SLOT)                                                   \
    {                                                                           \
        _Pragma("unroll")                                                       \
        for (int j = 0; j < 4; ++j) {                                           \
            const int sk = 4 * (FSI) + j;                                       \
            cp_async16(dstb + (SLOT) * STG_BYTES + j * 8192,                    \
                       psrc[sk >> 3] + ((sk & 7) << 3), szs[sk >> 3]);          \
        }                                                                       \
    }

    FILL_STAGE(0, 0); CP_COMMIT();
    FILL_STAGE(1, 1); CP_COMMIT();

    float acc[4][4][4];
    #pragma unroll
    for (int mt = 0; mt < 4; ++mt)
        #pragma unroll
        for (int nt = 0; nt < 4; ++nt)
            #pragma unroll
            for (int q = 0; q < 4; ++q)
                acc[mt][nt][q] = 0.0f;

    // per-warp invariant smem bases
    const uint32_t aw = as_addr + (uint32_t)(((wid & 1) * 4 * 32 + lane) * 16);
    const uint32_t bw = bs_addr + (uint32_t)(((row * 64 + nhalf + r) * 8 + cql) * 4);

    // ---- mainloop: 6 stages x 4 kc (fully unrolled) ----
    #pragma unroll
    for (int si = 0; si < NSTG; ++si) {
        CP_WAIT1();
        __syncthreads();

        if (si + LOOKA < NSTG) {
            const int fsi = si + LOOKA;
            const int fsl = (fsi >= RING) ? fsi - RING : fsi;
            FILL_STAGE(fsi, fsl);
        }
        CP_COMMIT();

        const int slot = (si >= RING) ? si - RING : si;

        #pragma unroll
        for (int j = 0; j < 4; ++j) {
            const int kc = 4 * si + j;
            const uint32_t ak = aw + (uint32_t)(kc * 4096);
            const uint32_t bk = bw + (uint32_t)(slot * STG_BYTES + j * 8192);

            uint32_t a[4][4];
            lds128(ak,        a[0]);
            lds128(ak + 512,  a[1]);
            lds128(ak + 1024, a[2]);
            lds128(ak + 1536, a[3]);

            uint32_t b0[4], b1[4];
            #pragma unroll
            for (int nt = 0; nt < 4; ++nt) {
                b0[nt] = lds32(bk + nt * 256);
                b1[nt] = lds32(bk + nt * 256 + 16);
            }

            #pragma unroll
            for (int nt = 0; nt < 4; ++nt)
                #pragma unroll
                for (int mt = 0; mt < 4; ++mt) {
                    asm volatile(
                        "mma.sync.aligned.m16n8k8.row.col.f32.tf32.tf32.f32 "
                        "{%0,%1,%2,%3}, {%4,%5,%6,%7}, {%8,%9}, {%0,%1,%2,%3};"
                        : "+f"(acc[mt][nt][0]), "+f"(acc[mt][nt][1]),
                          "+f"(acc[mt][nt][2]), "+f"(acc[mt][nt][3])
                        : "r"(a[mt][0]), "r"(a[mt][1]), "r"(a[mt][2]), "r"(a[mt][3]),
                          "r"(b0[nt]), "r"(b1[nt]));
                }
        }
    }

    __syncthreads();   // mainloop smem reads done; reuse smem for epilogue

    // ---- epilogue: bias + BN(t) + ReLU -> smem stage -> coalesced STG ----
    {
        const int n = n0c + row;
        const int t = n & (T_DIM - 1);
        const float inv = rsqrtf(bn_var[t] + BN_EPS);
        const float s   = bn_gamma[t] * inv;
        const float sh  = bn_beta[t] - bn_mean[t] * s;

        float* buf = smem + wid * EPI_WARP;   // [32 cp][68]

        #pragma unroll
        for (int mt = 0; mt < 4; ++mt) {
            const int ml = 16 * mt + r;
            const int mh = ml + 8;
            const float bl = conv_b[m0w + ml];
            const float bh = conv_b[m0w + mh];
            #pragma unroll
            for (int nt = 0; nt < 4; ++nt) {
                const int cp0 = 8 * nt + 2 * cql;
                buf[cp0       * EPI_PITCH + ml] = fmaxf((acc[mt][nt][0] + bl) * s + sh, 0.f);
                buf[(cp0 + 1) * EPI_PITCH + ml] = fmaxf((acc[mt][nt][1] + bl) * s + sh, 0.f);
                buf[cp0       * EPI_PITCH + mh] = fmaxf((acc[mt][nt][2] + bh) * s + sh, 0.f);
                buf[(cp0 + 1) * EPI_PITCH + mh] = fmaxf((acc[mt][nt][3] + bh) * s + sh, 0.f);
            }
        }
        __syncwarp();

        float* outn = out + (size_t)n * (CP * K_DIM) + m0w;
        const int cph = lane >> 4;            // 0/1
        const int m4  = 4 * (lane & 15);      // 0..60
        #pragma unroll
        for (int it = 0; it < 16; ++it) {
            const int cp  = 2 * it + cph;     // local 0..31
            const int cpg = nhalf + cp;
            if (cpg < CP) {
                const float4 v = *(const float4*)(buf + cp * EPI_PITCH + m4);
                *(float4*)(outn + cpg * K_DIM + m4) = v;
            }
        }
    }
}

extern "C" void kernel_launch(void* const* d_in, const int* in_sizes, int n_in,
                              void* d_out, int out_size)
{
    const float* x        = (const float*)d_in[0];
    const float* conv_w   = (const float*)d_in[1];
    const float* conv_b   = (const float*)d_in[2];
    const float* bn_gamma = (const float*)d_in[3];
    const float* bn_beta  = (const float*)d_in[4];
    const float* bn_mean  = (const float*)d_in[5];
    const float* bn_var   = (const float*)d_in[6];
    float* out = (float*)d_out;

    cudaFuncSetAttribute(tccnn_mma5_kernel,
                         cudaFuncAttributeMaxDynamicSharedMemorySize, SMEM_BYTES);

    tccnn_mma5_kernel<<<N_TOTAL / NROWS, THREADS, SMEM_BYTES>>>(
        x, conv_w, conv_b, bn_gamma, bn_beta, bn_mean, bn_var, out);
}

// round 14
// speedup vs baseline: 1.2815x; 1.2815x over previous
#include <cuda_runtime.h>
#include <cstdint>

// ---- problem constants ----
#define T_DIM   128
#define C_DIM   64
#define F_DIM   64
#define K_DIM   128          // filters = GEMM M
#define CP      62
#define N_TOTAL 4096
#define BN_EPS  1e-3f

#define NROWS   4            // fused rows per CTA -> GEMM N = 256
#define THREADS 512
#define NSTG    12           // stages of 2 kc (K = 192 = 24 kc)
#define RING    3
#define LOOKA   2

// B row stride 12 words (48B) -> conflict-free lds32 for (r, cql) lanes
#define BROW_W  12
// smem: Afrag[24][8][32][4] floats, then Bs[3][2 kc][256 n][12] floats
#define A_FLOATS 24576
#define STG_FLOATS (2 * 256 * BROW_W)    // 6144 floats = 24576 B
#define B_FLOATS (RING * STG_FLOATS)     // 18432
#define SMEM_BYTES ((A_FLOATS + B_FLOATS) * 4)   // 172032
#define STG_BYTES  (STG_FLOATS * 4)      // 24576
#define KC_BYTES   (256 * BROW_W * 4)    // 12288

// epilogue smem reuse: per-warp [32 cp][pitch 68]
#define EPI_PITCH 68
#define EPI_WARP  (32 * EPI_PITCH)

__device__ __forceinline__ uint32_t smem_u32(const void* p) {
    uint32_t a;
    asm("{ .reg .u64 t; cvta.to.shared.u64 t, %1; cvt.u32.u64 %0, t; }" : "=r"(a) : "l"(p));
    return a;
}
__device__ __forceinline__ float tf32r(float v) {
    uint32_t u;
    asm("cvt.rna.tf32.f32 %0, %1;" : "=r"(u) : "f"(v));
    return __uint_as_float(u);
}
__device__ __forceinline__ void cp_async16(uint32_t dst, const void* src, int sz) {
    asm volatile("cp.async.ca.shared.global [%0], [%1], 16, %2;"
                 :: "r"(dst), "l"(src), "r"(sz) : "memory");
}
#define CP_COMMIT() asm volatile("cp.async.commit_group;" ::: "memory")
#define CP_WAIT1()  asm volatile("cp.async.wait_group 1;" ::: "memory")

__device__ __forceinline__ void lds128(uint32_t a, uint32_t* v) {
    asm volatile("ld.shared.v4.b32 {%0,%1,%2,%3}, [%4];"
                 : "=r"(v[0]), "=r"(v[1]), "=r"(v[2]), "=r"(v[3]) : "r"(a));
}
__device__ __forceinline__ uint32_t lds32(uint32_t a) {
    uint32_t v;
    asm volatile("ld.shared.b32 %0, [%1];" : "=r"(v) : "r"(a));
    return v;
}

__global__ __launch_bounds__(THREADS, 1)
void tccnn_mma6_kernel(const float* __restrict__ x,
                       const float* __restrict__ conv_w,
                       const float* __restrict__ conv_b,
                       const float* __restrict__ bn_gamma,
                       const float* __restrict__ bn_beta,
                       const float* __restrict__ bn_mean,
                       const float* __restrict__ bn_var,
                       float* __restrict__ out)
{
    extern __shared__ float smem[];
    const uint32_t as_addr = smem_u32(smem);
    const uint32_t bs_addr = as_addr + A_FLOATS * 4;

    const int tid  = threadIdx.x;
    const int lane = tid & 31;
    const int wid  = tid >> 5;           // 0..15
    const int r    = lane >> 2;          // 0..7
    const int cql  = lane & 3;           // 0..3
    const int m0w  = (wid & 1) * 64;     // M origin: 2 m-warps
    const int nw   = wid >> 1;           // 0..7 n-slice
    const int row  = nw >> 1;            // fused row 0..3
    const int nhalf= (nw & 1) * 32;      // cp origin within row
    const int n0c  = blockIdx.x * NROWS;

    // ---- stage A as ready fragments:
    // frag f = kc*256 + mt8*32 + lane; [f] = {w[kl][ml], w[kl][ml+8], w[kh][ml], w[kh][ml+8]}
    #pragma unroll
    for (int i = 0; i < 12; ++i) {
        const int f   = tid + 512 * i;
        const int kc  = f >> 8;
        const int mt8 = (f >> 5) & 7;
        const int ln  = f & 31;
        const int kl  = 8 * kc + (ln & 3);
        const int kh2 = kl + 4;
        const int ml  = 16 * mt8 + (ln >> 2);
        float4 v;
        v.x = tf32r(conv_w[kl  * K_DIM + ml]);
        v.y = tf32r(conv_w[kl  * K_DIM + ml + 8]);
        v.z = tf32r(conv_w[kh2 * K_DIM + ml]);
        v.w = tf32r(conv_w[kh2 * K_DIM + ml + 8]);
        ((float4*)smem)[f] = v;
    }

    // ---- cp.async source/dst bases (per thread) ----
    const int nb   = tid >> 1;           // 0..255 = rowt*64 + cpt
    const int half = tid & 1;            // k 0-3 / 4-7 of the kc
    const int cpt  = nb & 63;
    const float* xrow = x + (size_t)(n0c + (nb >> 6)) * (C_DIM * F_DIM);
    const float* psrc[3];
    int szs[3];
    #pragma unroll
    for (int kh = 0; kh < 3; ++kh) {
        const int c  = cpt + kh;
        psrc[kh] = xrow + ((c < C_DIM) ? c : 0) * F_DIM + 4 * half;
        szs[kh]  = (c < C_DIM) ? 16 : 0;
    }
    const uint32_t dstb = bs_addr + (uint32_t)(48 * nb + 16 * half);

    // fill stage si (2 kc) into ring slot
    auto fill_stage = [&](int si, int slot) {
        #pragma unroll
        for (int j = 0; j < 2; ++j) {
            const int sk = 2 * si + j;
            cp_async16(dstb + slot * STG_BYTES + j * KC_BYTES,
                       psrc[sk >> 3] + ((sk & 7) << 3), szs[sk >> 3]);
        }
    };

    fill_stage(0, 0); CP_COMMIT();
    fill_stage(1, 1); CP_COMMIT();

    float acc[4][4][4];
    #pragma unroll
    for (int mt = 0; mt < 4; ++mt)
        #pragma unroll
        for (int nt = 0; nt < 4; ++nt)
            #pragma unroll
            for (int q = 0; q < 4; ++q)
                acc[mt][nt][q] = 0.0f;

    // per-warp invariant smem bases
    const uint32_t aw = as_addr + (uint32_t)(((wid & 1) * 4 * 32 + lane) * 16);
    const uint32_t bw = bs_addr + (uint32_t)(((row * 64 + nhalf + r) * BROW_W + cql) * 4);

    int slot = 0, fslot = 2;

    // ---- mainloop: 12 stages x 2 kc ----
    #pragma unroll 1
    for (int si = 0; si < NSTG; ++si) {
        CP_WAIT1();                 // stage si resident
        __syncthreads();            // visible to all (covers A on si=0)

        if (si + LOOKA < NSTG)
            fill_stage(si + LOOKA, fslot);
        CP_COMMIT();                // always commit to keep group count exact

        const uint32_t bst = bw + (uint32_t)(slot * STG_BYTES);

        // prefetch B frags for kc j=0
        float bb[2][8];
        #pragma unroll
        for (int nt = 0; nt < 4; ++nt) {
            bb[0][2 * nt]     = __uint_as_float(lds32(bst + nt * (8 * BROW_W * 4)));
            bb[0][2 * nt + 1] = __uint_as_float(lds32(bst + nt * (8 * BROW_W * 4) + 16));
        }

        #pragma unroll
        for (int j = 0; j < 2; ++j) {
            if (j < 1) {
                #pragma unroll
                for (int nt = 0; nt < 4; ++nt) {
                    bb[1][2 * nt]     = __uint_as_float(lds32(bst + KC_BYTES + nt * (8 * BROW_W * 4)));
                    bb[1][2 * nt + 1] = __uint_as_float(lds32(bst + KC_BYTES + nt * (8 * BROW_W * 4) + 16));
                }
            }

            const uint32_t ak = aw + (uint32_t)((2 * si + j) * 4096);
            uint32_t a[4][4];
            lds128(ak,        a[0]);
            lds128(ak + 512,  a[1]);
            lds128(ak + 1024, a[2]);
            lds128(ak + 1536, a[3]);

            const float* bj = bb[j];
            #pragma unroll
            for (int nt = 0; nt < 4; ++nt) {
                const uint32_t b0 = __float_as_uint(bj[2 * nt]);
                const uint32_t b1 = __float_as_uint(bj[2 * nt + 1]);
                #pragma unroll
                for (int mt = 0; mt < 4; ++mt) {
                    asm volatile(
                        "mma.sync.aligned.m16n8k8.row.col.f32.tf32.tf32.f32 "
                        "{%0,%1,%2,%3}, {%4,%5,%6,%7}, {%8,%9}, {%0,%1,%2,%3};"
                        : "+f"(acc[mt][nt][0]), "+f"(acc[mt][nt][1]),
                          "+f"(acc[mt][nt][2]), "+f"(acc[mt][nt][3])
                        : "r"(a[mt][0]), "r"(a[mt][1]), "r"(a[mt][2]), "r"(a[mt][3]),
                          "r"(b0), "r"(b1));
                }
            }
        }

        slot  = (slot == RING - 1) ? 0 : slot + 1;
        fslot = (fslot == RING - 1) ? 0 : fslot + 1;
    }

    __syncthreads();   // mainloop smem reads done; reuse smem for epilogue

    // ---- epilogue: bias + BN(t) + ReLU -> smem stage -> coalesced STG ----
    {
        const int n = n0c + row;
        const int t = n & (T_DIM - 1);
        const float inv = rsqrtf(bn_var[t] + BN_EPS);
        const float s   = bn_gamma[t] * inv;
        const float sh  = bn_beta[t] - bn_mean[t] * s;

        float* buf = smem + wid * EPI_WARP;   // [32 cp][68]

        #pragma unroll
        for (int mt = 0; mt < 4; ++mt) {
            const int ml = 16 * mt + r;
            const int mh = ml + 8;
            const float bl = conv_b[m0w + ml];
            const float bh = conv_b[m0w + mh];
            #pragma unroll
            for (int nt = 0; nt < 4; ++nt) {
                const int cp0 = 8 * nt + 2 * cql;
                buf[cp0       * EPI_PITCH + ml] = fmaxf((acc[mt][nt][0] + bl) * s + sh, 0.f);
                buf[(cp0 + 1) * EPI_PITCH + ml] = fmaxf((acc[mt][nt][1] + bl) * s + sh, 0.f);
                buf[cp0       * EPI_PITCH + mh] = fmaxf((acc[mt][nt][2] + bh) * s + sh, 0.f);
                buf[(cp0 + 1) * EPI_PITCH + mh] = fmaxf((acc[mt][nt][3] + bh) * s + sh, 0.f);
            }
        }
        __syncwarp();

        float* outn = out + (size_t)n * (CP * K_DIM) + m0w;
        const int cph = lane >> 4;            // 0/1
        const int m4  = 4 * (lane & 15);      // 0..60
        #pragma unroll
        for (int it = 0; it < 16; ++it) {
            const int cp  = 2 * it + cph;     // local 0..31
            const int cpg = nhalf + cp;
            if (cpg < CP) {
                const float4 v = *(const float4*)(buf + cp * EPI_PITCH + m4);
                *(float4*)(outn + cpg * K_DIM + m4) = v;
            }
        }
    }
}

extern "C" void kernel_launch(void* const* d_in, const int* in_sizes, int n_in,
                              void* d_out, int out_size)
{
    const float* x        = (const float*)d_in[0];
    const float* conv_w   = (const float*)d_in[1];
    const float* conv_b   = (const float*)d_in[2];
    const float* bn_gamma = (const float*)d_in[3];
    const float* bn_beta  = (const float*)d_in[4];
    const float* bn_mean  = (const float*)d_in[5];
    const float* bn_var   = (const float*)d_in[6];
    float* out = (float*)d_out;

    cudaFuncSetAttribute(tccnn_mma6_kernel,
                         cudaFuncAttributeMaxDynamicSharedMemorySize, SMEM_BYTES);

    tccnn_mma6_kernel<<<N_TOTAL / NROWS, THREADS, SMEM_BYTES>>>(
        x, conv_w, conv_b, bn_gamma, bn_beta, bn_mean, bn_var, out);
}